// round 2
// baseline (speedup 1.0000x reference)
#include <cuda_runtime.h>
#include <math.h>
#include <float.h>

// Problem constants
#define B_  4
#define S_  2048
#define H_  16
#define DK_ 64
#define D_  1024
#define M_  (B_*S_)   // 8192 rows

// Scratch (device globals: no allocation allowed in kernel_launch)
__device__ float g_Q [(size_t)M_ * D_];
__device__ float g_K [(size_t)M_ * D_];
__device__ float g_V [(size_t)M_ * D_];
__device__ float g_AO[(size_t)M_ * D_];

// ----------------------------------------------------------------------------
// SGEMM + bias: C[M,N] = A[M,K] @ W[K,N] + bias[N]
// 128x128 block tile, K-step 8, 256 threads, 8x8 per thread.
// ----------------------------------------------------------------------------
__global__ __launch_bounds__(256, 2)
void sgemm_bias_kernel(const float* __restrict__ A, const float* __restrict__ W,
                       const float* __restrict__ bias, float* __restrict__ C,
                       int M, int N, int K)
{
    __shared__ float As[8][128];   // transposed A tile: As[kk][m]
    __shared__ float Bs[8][128];   // Bs[kk][n]

    const int tid = threadIdx.x;
    const int tr  = tid >> 4;          // 0..15  -> row group (8 rows)
    const int tc  = tid & 15;          // 0..15  -> col group (8 cols)
    const int m0  = blockIdx.y * 128;
    const int n0  = blockIdx.x * 128;

    const int a_row = tid >> 1;            // 0..127
    const int a_col = (tid & 1) * 4;       // 0 or 4
    const int b_row = tid >> 5;            // 0..7
    const int b_col = (tid & 31) * 4;      // 0..124

    const float* Aptr = A + (size_t)(m0 + a_row) * K + a_col;
    const float* Wptr = W + (size_t)b_row * N + n0 + b_col;

    float acc[8][8];
#pragma unroll
    for (int i = 0; i < 8; i++)
#pragma unroll
        for (int j = 0; j < 8; j++) acc[i][j] = 0.f;

    for (int k0 = 0; k0 < K; k0 += 8) {
        float4 av = *(const float4*)(Aptr + k0);
        As[a_col + 0][a_row] = av.x;
        As[a_col + 1][a_row] = av.y;
        As[a_col + 2][a_row] = av.z;
        As[a_col + 3][a_row] = av.w;
        *(float4*)&Bs[b_row][b_col] = *(const float4*)(Wptr + (size_t)k0 * N);
        __syncthreads();

#pragma unroll
        for (int kk = 0; kk < 8; kk++) {
            float a[8], bb[8];
            *(float4*)&a[0]  = *(const float4*)&As[kk][tr * 8];
            *(float4*)&a[4]  = *(const float4*)&As[kk][tr * 8 + 4];
            *(float4*)&bb[0] = *(const float4*)&Bs[kk][tc * 8];
            *(float4*)&bb[4] = *(const float4*)&Bs[kk][tc * 8 + 4];
#pragma unroll
            for (int i = 0; i < 8; i++)
#pragma unroll
                for (int j = 0; j < 8; j++)
                    acc[i][j] = fmaf(a[i], bb[j], acc[i][j]);
        }
        __syncthreads();
    }

    float bj[8];
#pragma unroll
    for (int j = 0; j < 8; j++) bj[j] = bias[n0 + tc * 8 + j];

#pragma unroll
    for (int i = 0; i < 8; i++) {
        float* cp = C + (size_t)(m0 + tr * 8 + i) * N + n0 + tc * 8;
        float4 v0, v1;
        v0.x = acc[i][0] + bj[0]; v0.y = acc[i][1] + bj[1];
        v0.z = acc[i][2] + bj[2]; v0.w = acc[i][3] + bj[3];
        v1.x = acc[i][4] + bj[4]; v1.y = acc[i][5] + bj[5];
        v1.z = acc[i][6] + bj[6]; v1.w = acc[i][7] + bj[7];
        *(float4*)cp       = v0;
        *(float4*)(cp + 4) = v1;
    }
}

// ----------------------------------------------------------------------------
// Flash attention (fp32, online softmax).
// One CTA = (b, h, 64 q-rows). KV tiles of 64. 256 threads.
// Thread (ty = tid>>2 -> q-row, tx = tid&3 -> 16-col group of DK=64).
// ----------------------------------------------------------------------------
#define QT    64
#define KT    64
#define PITCH 68   // float pitch: float4-aligned, kills row bank conflicts

extern __shared__ float fa_sm[];

__global__ __launch_bounds__(256)
void flash_attn_kernel(const float* __restrict__ Q, const float* __restrict__ K,
                       const float* __restrict__ V, float* __restrict__ O)
{
    float* Qs = fa_sm;                    // [64][PITCH]  Q rows (dk-minor)
    float* Kt = Qs + 64 * PITCH;          // [64][PITCH]  K transposed: Kt[dk][key]
    float* Vs = Kt + 64 * PITCH;          // [64][PITCH]  V natural: Vs[key][dk]
    float* Ps = Vs + 64 * PITCH;          // [64][PITCH]  probs

    const int tid  = threadIdx.x;
    const int q0   = blockIdx.x * QT;
    const int h    = blockIdx.y;
    const int b    = blockIdx.z;
    const int hoff = h * DK_;
    const int ty   = tid >> 2;   // q-row within tile
    const int tx   = tid & 3;    // col group: cols tx*16 .. tx*16+15

    // Load Q tile (64x64), natural layout
#pragma unroll
    for (int i = 0; i < 4; i++) {
        int idx = tid + i * 256;
        int row = idx >> 4;
        int cg  = (idx & 15) * 4;
        float4 v = *(const float4*)&Q[(size_t)(b * S_ + q0 + row) * D_ + hoff + cg];
        *(float4*)&Qs[row * PITCH + cg] = v;
    }

    float m = -FLT_MAX;
    float l = 0.f;
    float o[16];
#pragma unroll
    for (int j = 0; j < 16; j++) o[j] = 0.f;

    for (int kt = 0; kt < S_; kt += KT) {
        __syncthreads();  // protect prior-iter Ps/Vs reads (and Qs stores on iter 0)

        // Load K (transposed -> Kt[dk][key]) and V (natural) tiles
#pragma unroll
        for (int i = 0; i < 4; i++) {
            int idx = tid + i * 256;
            int row = idx >> 4;           // key index within tile
            int cg  = (idx & 15) * 4;     // dk group
            const size_t gr = (size_t)(b * S_ + kt + row) * D_ + hoff + cg;
            float4 kv = *(const float4*)&K[gr];
            Kt[(cg + 0) * PITCH + row] = kv.x;
            Kt[(cg + 1) * PITCH + row] = kv.y;
            Kt[(cg + 2) * PITCH + row] = kv.z;
            Kt[(cg + 3) * PITCH + row] = kv.w;
            float4 vv = *(const float4*)&V[gr];
            *(float4*)&Vs[row * PITCH + cg] = vv;
        }
        __syncthreads();

        // s[j] = Q[ty,:] . K[tx*16+j,:]   (2-way k unroll for LDS MLP)
        float s[16];
#pragma unroll
        for (int j = 0; j < 16; j++) s[j] = 0.f;
        const float* qrow = &Qs[ty * PITCH];
#pragma unroll 2
        for (int kk = 0; kk < 64; kk += 2) {
            float qv0 = qrow[kk];
            float qv1 = qrow[kk + 1];
            const float* kr0 = &Kt[kk * PITCH + tx * 16];
            const float* kr1 = kr0 + PITCH;
            float4 a0 = *(const float4*)&kr0[0];
            float4 a1 = *(const float4*)&kr0[4];
            float4 a2 = *(const float4*)&kr0[8];
            float4 a3 = *(const float4*)&kr0[12];
            float4 c0 = *(const float4*)&kr1[0];
            float4 c1 = *(const float4*)&kr1[4];
            float4 c2 = *(const float4*)&kr1[8];
            float4 c3 = *(const float4*)&kr1[12];
            s[0]  = fmaf(qv0, a0.x, s[0]);  s[1]  = fmaf(qv0, a0.y, s[1]);
            s[2]  = fmaf(qv0, a0.z, s[2]);  s[3]  = fmaf(qv0, a0.w, s[3]);
            s[4]  = fmaf(qv0, a1.x, s[4]);  s[5]  = fmaf(qv0, a1.y, s[5]);
            s[6]  = fmaf(qv0, a1.z, s[6]);  s[7]  = fmaf(qv0, a1.w, s[7]);
            s[8]  = fmaf(qv0, a2.x, s[8]);  s[9]  = fmaf(qv0, a2.y, s[9]);
            s[10] = fmaf(qv0, a2.z, s[10]); s[11] = fmaf(qv0, a2.w, s[11]);
            s[12] = fmaf(qv0, a3.x, s[12]); s[13] = fmaf(qv0, a3.y, s[13]);
            s[14] = fmaf(qv0, a3.z, s[14]); s[15] = fmaf(qv0, a3.w, s[15]);
            s[0]  = fmaf(qv1, c0.x, s[0]);  s[1]  = fmaf(qv1, c0.y, s[1]);
            s[2]  = fmaf(qv1, c0.z, s[2]);  s[3]  = fmaf(qv1, c0.w, s[3]);
            s[4]  = fmaf(qv1, c1.x, s[4]);  s[5]  = fmaf(qv1, c1.y, s[5]);
            s[6]  = fmaf(qv1, c1.z, s[6]);  s[7]  = fmaf(qv1, c1.w, s[7]);
            s[8]  = fmaf(qv1, c2.x, s[8]);  s[9]  = fmaf(qv1, c2.y, s[9]);
            s[10] = fmaf(qv1, c2.z, s[10]); s[11] = fmaf(qv1, c2.w, s[11]);
            s[12] = fmaf(qv1, c3.x, s[12]); s[13] = fmaf(qv1, c3.y, s[13]);
            s[14] = fmaf(qv1, c3.z, s[14]); s[15] = fmaf(qv1, c3.w, s[15]);
        }

        // scale + row max (across the 4-thread row group)
        float tmax = -FLT_MAX;
#pragma unroll
        for (int j = 0; j < 16; j++) {
            s[j] *= 0.125f;   // 1/sqrt(64)
            tmax = fmaxf(tmax, s[j]);
        }
        tmax = fmaxf(tmax, __shfl_xor_sync(0xffffffffu, tmax, 1));
        tmax = fmaxf(tmax, __shfl_xor_sync(0xffffffffu, tmax, 2));

        float mn    = fmaxf(m, tmax);
        float alpha = __expf(m - mn);       // first tile: exp(-inf) = 0
        float psum  = 0.f;
#pragma unroll
        for (int j = 0; j < 16; j++) {
            float p = __expf(s[j] - mn);
            s[j] = p;
            psum += p;
        }
        psum += __shfl_xor_sync(0xffffffffu, psum, 1);
        psum += __shfl_xor_sync(0xffffffffu, psum, 2);
        l = l * alpha + psum;
        m = mn;
#pragma unroll
        for (int j = 0; j < 16; j++) o[j] *= alpha;

        // publish probs
        float* prow = &Ps[ty * PITCH + tx * 16];
        *(float4*)&prow[0]  = make_float4(s[0],  s[1],  s[2],  s[3]);
        *(float4*)&prow[4]  = make_float4(s[4],  s[5],  s[6],  s[7]);
        *(float4*)&prow[8]  = make_float4(s[8],  s[9],  s[10], s[11]);
        *(float4*)&prow[12] = make_float4(s[12], s[13], s[14], s[15]);
        __syncthreads();

        // O[ty, c] += sum_k P[ty,k] * V[k,c]   (2-way k unroll for LDS MLP)
        const float* psrow = &Ps[ty * PITCH];
#pragma unroll 2
        for (int k = 0; k < 64; k += 2) {
            float p0 = psrow[k];
            float p1 = psrow[k + 1];
            const float* vr0 = &Vs[k * PITCH + tx * 16];
            const float* vr1 = vr0 + PITCH;
            float4 a0 = *(const float4*)&vr0[0];
            float4 a1 = *(const float4*)&vr0[4];
            float4 a2 = *(const float4*)&vr0[8];
            float4 a3 = *(const float4*)&vr0[12];
            float4 c0 = *(const float4*)&vr1[0];
            float4 c1 = *(const float4*)&vr1[4];
            float4 c2 = *(const float4*)&vr1[8];
            float4 c3 = *(const float4*)&vr1[12];
            o[0]  = fmaf(p0, a0.x, o[0]);  o[1]  = fmaf(p0, a0.y, o[1]);
            o[2]  = fmaf(p0, a0.z, o[2]);  o[3]  = fmaf(p0, a0.w, o[3]);
            o[4]  = fmaf(p0, a1.x, o[4]);  o[5]  = fmaf(p0, a1.y, o[5]);
            o[6]  = fmaf(p0, a1.z, o[6]);  o[7]  = fmaf(p0, a1.w, o[7]);
            o[8]  = fmaf(p0, a2.x, o[8]);  o[9]  = fmaf(p0, a2.y, o[9]);
            o[10] = fmaf(p0, a2.z, o[10]); o[11] = fmaf(p0, a2.w, o[11]);
            o[12] = fmaf(p0, a3.x, o[12]); o[13] = fmaf(p0, a3.y, o[13]);
            o[14] = fmaf(p0, a3.z, o[14]); o[15] = fmaf(p0, a3.w, o[15]);
            o[0]  = fmaf(p1, c0.x, o[0]);  o[1]  = fmaf(p1, c0.y, o[1]);
            o[2]  = fmaf(p1, c0.z, o[2]);  o[3]  = fmaf(p1, c0.w, o[3]);
            o[4]  = fmaf(p1, c1.x, o[4]);  o[5]  = fmaf(p1, c1.y, o[5]);
            o[6]  = fmaf(p1, c1.z, o[6]);  o[7]  = fmaf(p1, c1.w, o[7]);
            o[8]  = fmaf(p1, c2.x, o[8]);  o[9]  = fmaf(p1, c2.y, o[9]);
            o[10] = fmaf(p1, c2.z, o[10]); o[11] = fmaf(p1, c2.w, o[11]);
            o[12] = fmaf(p1, c3.x, o[12]); o[13] = fmaf(p1, c3.y, o[13]);
            o[14] = fmaf(p1, c3.z, o[14]); o[15] = fmaf(p1, c3.w, o[15]);
        }
    }

    // normalize + write to [B,S,D] layout (head-interleaved columns)
    float inv = 1.f / l;
    float* op = &O[(size_t)(b * S_ + q0 + ty) * D_ + hoff + tx * 16];
    *(float4*)&op[0]  = make_float4(o[0]*inv,  o[1]*inv,  o[2]*inv,  o[3]*inv);
    *(float4*)&op[4]  = make_float4(o[4]*inv,  o[5]*inv,  o[6]*inv,  o[7]*inv);
    *(float4*)&op[8]  = make_float4(o[8]*inv,  o[9]*inv,  o[10]*inv, o[11]*inv);
    *(float4*)&op[12] = make_float4(o[12]*inv, o[13]*inv, o[14]*inv, o[15]*inv);
}

// ----------------------------------------------------------------------------
// Launch: 3 projection GEMMs -> flash attention -> output GEMM
// Input order (metadata): query, value, key, Wq, bq, Wk, bk, Wv, bv, Wo, bo
// ----------------------------------------------------------------------------
extern "C" void kernel_launch(void* const* d_in, const int* in_sizes, int n_in,
                              void* d_out, int out_size)
{
    const float* query = (const float*)d_in[0];
    const float* value = (const float*)d_in[1];
    const float* key   = (const float*)d_in[2];
    const float* Wq = (const float*)d_in[3];
    const float* bq = (const float*)d_in[4];
    const float* Wk = (const float*)d_in[5];
    const float* bk = (const float*)d_in[6];
    const float* Wv = (const float*)d_in[7];
    const float* bv = (const float*)d_in[8];
    const float* Wo = (const float*)d_in[9];
    const float* bo = (const float*)d_in[10];
    float* out = (float*)d_out;

    float *Qp, *Kp, *Vp, *AOp;
    cudaGetSymbolAddress((void**)&Qp,  g_Q);
    cudaGetSymbolAddress((void**)&Kp,  g_K);
    cudaGetSymbolAddress((void**)&Vp,  g_V);
    cudaGetSymbolAddress((void**)&AOp, g_AO);

    dim3 gemm_grid(D_ / 128, M_ / 128);
    sgemm_bias_kernel<<<gemm_grid, 256>>>(query, Wq, bq, Qp, M_, D_, D_);
    sgemm_bias_kernel<<<gemm_grid, 256>>>(key,   Wk, bk, Kp, M_, D_, D_);
    sgemm_bias_kernel<<<gemm_grid, 256>>>(value, Wv, bv, Vp, M_, D_, D_);

    const int fa_smem = 4 * 64 * PITCH * (int)sizeof(float);  // ~69.6 KB
    cudaFuncSetAttribute(flash_attn_kernel,
                         cudaFuncAttributeMaxDynamicSharedMemorySize, fa_smem);
    flash_attn_kernel<<<dim3(S_ / QT, H_, B_), 256, fa_smem>>>(Qp, Kp, Vp, AOp);

    sgemm_bias_kernel<<<gemm_grid, 256>>>(AOp, Wo, bo, out, M_, D_, D_);
}

// round 3
// speedup vs baseline: 1.7230x; 1.7230x over previous
#include <cuda_runtime.h>
#include <math.h>
#include <float.h>

// Problem constants
#define B_  4
#define S_  2048
#define H_  16
#define DK_ 64
#define D_  1024
#define M_  (B_*S_)   // 8192 rows

// Scratch (device globals: no allocation allowed in kernel_launch)
__device__ float g_Q [(size_t)M_ * D_];
__device__ float g_K [(size_t)M_ * D_];
__device__ float g_V [(size_t)M_ * D_];
__device__ float g_AO[(size_t)M_ * D_];

// ----------------------------------------------------------------------------
// SGEMM + bias: C[M,N] = A[M,K] @ W[K,N] + bias[N]
// 128x128 block tile, K-step 8, 256 threads, 8x8 per thread.
// Double-buffered smem: one __syncthreads per K-step, global prefetch
// overlapped with the FFMA block.
// ----------------------------------------------------------------------------
__global__ __launch_bounds__(256, 2)
void sgemm_bias_kernel(const float* __restrict__ A, const float* __restrict__ W,
                       const float* __restrict__ bias, float* __restrict__ C,
                       int M, int N, int K)
{
    __shared__ float As[2][8][128];   // transposed A tile: As[buf][kk][m]
    __shared__ float Bs[2][8][128];   // Bs[buf][kk][n]

    const int tid = threadIdx.x;
    const int tr  = tid >> 4;          // 0..15  -> row group (8 rows)
    const int tc  = tid & 15;          // 0..15  -> col group (8 cols)
    const int m0  = blockIdx.y * 128;
    const int n0  = blockIdx.x * 128;

    const int a_row = tid >> 1;            // 0..127
    const int a_col = (tid & 1) * 4;       // 0 or 4
    const int b_row = tid >> 5;            // 0..7
    const int b_col = (tid & 31) * 4;      // 0..124

    const float* Aptr = A + (size_t)(m0 + a_row) * K + a_col;
    const float* Wptr = W + (size_t)b_row * N + n0 + b_col;

    float acc[8][8];
#pragma unroll
    for (int i = 0; i < 8; i++)
#pragma unroll
        for (int j = 0; j < 8; j++) acc[i][j] = 0.f;

    // Preload first tile into buffer 0
    {
        float4 av = *(const float4*)(Aptr);
        As[0][a_col + 0][a_row] = av.x;
        As[0][a_col + 1][a_row] = av.y;
        As[0][a_col + 2][a_row] = av.z;
        As[0][a_col + 3][a_row] = av.w;
        *(float4*)&Bs[0][b_row][b_col] = *(const float4*)(Wptr);
    }
    __syncthreads();

    int cur = 0;
    for (int k0 = 8; k0 < K; k0 += 8) {
        // Prefetch next tile from global (latency hidden under compute)
        float4 av2 = *(const float4*)(Aptr + k0);
        float4 bv2 = *(const float4*)(Wptr + (size_t)k0 * N);

#pragma unroll
        for (int kk = 0; kk < 8; kk++) {
            float a[8], bb[8];
            *(float4*)&a[0]  = *(const float4*)&As[cur][kk][tr * 8];
            *(float4*)&a[4]  = *(const float4*)&As[cur][kk][tr * 8 + 4];
            *(float4*)&bb[0] = *(const float4*)&Bs[cur][kk][tc * 8];
            *(float4*)&bb[4] = *(const float4*)&Bs[cur][kk][tc * 8 + 4];
#pragma unroll
            for (int i = 0; i < 8; i++)
#pragma unroll
                for (int j = 0; j < 8; j++)
                    acc[i][j] = fmaf(a[i], bb[j], acc[i][j]);
        }

        int nxt = cur ^ 1;
        As[nxt][a_col + 0][a_row] = av2.x;
        As[nxt][a_col + 1][a_row] = av2.y;
        As[nxt][a_col + 2][a_row] = av2.z;
        As[nxt][a_col + 3][a_row] = av2.w;
        *(float4*)&Bs[nxt][b_row][b_col] = bv2;
        __syncthreads();
        cur = nxt;
    }

    // Last tile
#pragma unroll
    for (int kk = 0; kk < 8; kk++) {
        float a[8], bb[8];
        *(float4*)&a[0]  = *(const float4*)&As[cur][kk][tr * 8];
        *(float4*)&a[4]  = *(const float4*)&As[cur][kk][tr * 8 + 4];
        *(float4*)&bb[0] = *(const float4*)&Bs[cur][kk][tc * 8];
        *(float4*)&bb[4] = *(const float4*)&Bs[cur][kk][tc * 8 + 4];
#pragma unroll
        for (int i = 0; i < 8; i++)
#pragma unroll
            for (int j = 0; j < 8; j++)
                acc[i][j] = fmaf(a[i], bb[j], acc[i][j]);
    }

    float bj[8];
#pragma unroll
    for (int j = 0; j < 8; j++) bj[j] = bias[n0 + tc * 8 + j];

#pragma unroll
    for (int i = 0; i < 8; i++) {
        float* cp = C + (size_t)(m0 + tr * 8 + i) * N + n0 + tc * 8;
        float4 v0, v1;
        v0.x = acc[i][0] + bj[0]; v0.y = acc[i][1] + bj[1];
        v0.z = acc[i][2] + bj[2]; v0.w = acc[i][3] + bj[3];
        v1.x = acc[i][4] + bj[4]; v1.y = acc[i][5] + bj[5];
        v1.z = acc[i][6] + bj[6]; v1.w = acc[i][7] + bj[7];
        *(float4*)cp       = v0;
        *(float4*)(cp + 4) = v1;
    }
}

// ----------------------------------------------------------------------------
// Flash attention (fp32, online softmax), 2 q-rows per thread.
// One CTA = (b, h, 128 q-rows). KV tiles of 64. 256 threads.
// Thread (ty = tid>>2 -> q-rows {ty, ty+64}, tx = tid&3 -> 16-col group).
// Each K/V shared read now feeds 32 FMAs (was 16) -> halves smem traffic/FMA.
// ----------------------------------------------------------------------------
#define QT    128
#define KT    64
#define PITCH 68   // float pitch: float4-aligned, kills row bank conflicts

extern __shared__ float fa_sm[];

__global__ __launch_bounds__(256, 2)
void flash_attn_kernel(const float* __restrict__ Q, const float* __restrict__ K,
                       const float* __restrict__ V, float* __restrict__ O)
{
    float* Qs = fa_sm;                    // [128][PITCH]  Q rows (dk-minor)
    float* Kt = Qs + 128 * PITCH;         // [64][PITCH]   K transposed: Kt[dk][key]
    float* Vs = Kt + 64 * PITCH;          // [64][PITCH]   V natural: Vs[key][dk]
    float* Ps = Vs + 64 * PITCH;          // [128][PITCH]  probs

    const int tid  = threadIdx.x;
    const int q0   = blockIdx.x * QT;
    const int h    = blockIdx.y;
    const int b    = blockIdx.z;
    const int hoff = h * DK_;
    const int ty   = tid >> 2;   // q-row pair base: rows ty and ty+64
    const int tx   = tid & 3;    // col group: cols tx*16 .. tx*16+15

    // Load Q tile (128x64), natural layout
#pragma unroll
    for (int i = 0; i < 8; i++) {
        int idx = tid + i * 256;
        int row = idx >> 4;
        int cg  = (idx & 15) * 4;
        float4 v = *(const float4*)&Q[(size_t)(b * S_ + q0 + row) * D_ + hoff + cg];
        *(float4*)&Qs[row * PITCH + cg] = v;
    }

    float m0r = -FLT_MAX, m1r = -FLT_MAX;
    float l0  = 0.f,      l1  = 0.f;
    float o0[16], o1[16];
#pragma unroll
    for (int j = 0; j < 16; j++) { o0[j] = 0.f; o1[j] = 0.f; }

    for (int kt = 0; kt < S_; kt += KT) {
        __syncthreads();  // prior-iter Ps/Vs reads done (and Qs stores on iter 0)

        // Load K (transposed -> Kt[dk][key]) and V (natural) tiles
#pragma unroll
        for (int i = 0; i < 4; i++) {
            int idx = tid + i * 256;
            int row = idx >> 4;           // key index within tile
            int cg  = (idx & 15) * 4;     // dk group
            const size_t gr = (size_t)(b * S_ + kt + row) * D_ + hoff + cg;
            float4 kv = *(const float4*)&K[gr];
            Kt[(cg + 0) * PITCH + row] = kv.x;
            Kt[(cg + 1) * PITCH + row] = kv.y;
            Kt[(cg + 2) * PITCH + row] = kv.z;
            Kt[(cg + 3) * PITCH + row] = kv.w;
            float4 vv = *(const float4*)&V[gr];
            *(float4*)&Vs[row * PITCH + cg] = vv;
        }
        __syncthreads();

        // s{0,1}[j] = Q[row,:] . K[tx*16+j,:] for rows ty, ty+64
        float s0[16], s1[16];
#pragma unroll
        for (int j = 0; j < 16; j++) { s0[j] = 0.f; s1[j] = 0.f; }
        const float* q0r = &Qs[ty * PITCH];
        const float* q1r = &Qs[(ty + 64) * PITCH];
        for (int kk = 0; kk < 64; kk++) {
            float qa = q0r[kk];
            float qb = q1r[kk];
            const float* kr = &Kt[kk * PITCH + tx * 16];
            float4 k0 = *(const float4*)&kr[0];
            float4 k1 = *(const float4*)&kr[4];
            float4 k2 = *(const float4*)&kr[8];
            float4 k3 = *(const float4*)&kr[12];
            s0[0]  = fmaf(qa, k0.x, s0[0]);  s0[1]  = fmaf(qa, k0.y, s0[1]);
            s0[2]  = fmaf(qa, k0.z, s0[2]);  s0[3]  = fmaf(qa, k0.w, s0[3]);
            s0[4]  = fmaf(qa, k1.x, s0[4]);  s0[5]  = fmaf(qa, k1.y, s0[5]);
            s0[6]  = fmaf(qa, k1.z, s0[6]);  s0[7]  = fmaf(qa, k1.w, s0[7]);
            s0[8]  = fmaf(qa, k2.x, s0[8]);  s0[9]  = fmaf(qa, k2.y, s0[9]);
            s0[10] = fmaf(qa, k2.z, s0[10]); s0[11] = fmaf(qa, k2.w, s0[11]);
            s0[12] = fmaf(qa, k3.x, s0[12]); s0[13] = fmaf(qa, k3.y, s0[13]);
            s0[14] = fmaf(qa, k3.z, s0[14]); s0[15] = fmaf(qa, k3.w, s0[15]);
            s1[0]  = fmaf(qb, k0.x, s1[0]);  s1[1]  = fmaf(qb, k0.y, s1[1]);
            s1[2]  = fmaf(qb, k0.z, s1[2]);  s1[3]  = fmaf(qb, k0.w, s1[3]);
            s1[4]  = fmaf(qb, k1.x, s1[4]);  s1[5]  = fmaf(qb, k1.y, s1[5]);
            s1[6]  = fmaf(qb, k1.z, s1[6]);  s1[7]  = fmaf(qb, k1.w, s1[7]);
            s1[8]  = fmaf(qb, k2.x, s1[8]);  s1[9]  = fmaf(qb, k2.y, s1[9]);
            s1[10] = fmaf(qb, k2.z, s1[10]); s1[11] = fmaf(qb, k2.w, s1[11]);
            s1[12] = fmaf(qb, k3.x, s1[12]); s1[13] = fmaf(qb, k3.y, s1[13]);
            s1[14] = fmaf(qb, k3.z, s1[14]); s1[15] = fmaf(qb, k3.w, s1[15]);
        }

        // scale + row max (across the 4-thread row group), per row
        float t0 = -FLT_MAX, t1 = -FLT_MAX;
#pragma unroll
        for (int j = 0; j < 16; j++) {
            s0[j] *= 0.125f;   // 1/sqrt(64)
            s1[j] *= 0.125f;
            t0 = fmaxf(t0, s0[j]);
            t1 = fmaxf(t1, s1[j]);
        }
        t0 = fmaxf(t0, __shfl_xor_sync(0xffffffffu, t0, 1));
        t0 = fmaxf(t0, __shfl_xor_sync(0xffffffffu, t0, 2));
        t1 = fmaxf(t1, __shfl_xor_sync(0xffffffffu, t1, 1));
        t1 = fmaxf(t1, __shfl_xor_sync(0xffffffffu, t1, 2));

        float mn0 = fmaxf(m0r, t0);
        float mn1 = fmaxf(m1r, t1);
        float al0 = __expf(m0r - mn0);   // first tile: exp(-inf) = 0
        float al1 = __expf(m1r - mn1);
        float ps0 = 0.f, ps1 = 0.f;
#pragma unroll
        for (int j = 0; j < 16; j++) {
            float p0 = __expf(s0[j] - mn0);
            float p1 = __expf(s1[j] - mn1);
            s0[j] = p0;  ps0 += p0;
            s1[j] = p1;  ps1 += p1;
        }
        ps0 += __shfl_xor_sync(0xffffffffu, ps0, 1);
        ps0 += __shfl_xor_sync(0xffffffffu, ps0, 2);
        ps1 += __shfl_xor_sync(0xffffffffu, ps1, 1);
        ps1 += __shfl_xor_sync(0xffffffffu, ps1, 2);
        l0 = l0 * al0 + ps0;  m0r = mn0;
        l1 = l1 * al1 + ps1;  m1r = mn1;
#pragma unroll
        for (int j = 0; j < 16; j++) { o0[j] *= al0; o1[j] *= al1; }

        // publish probs (both rows)
        {
            float* pr0 = &Ps[ty * PITCH + tx * 16];
            float* pr1 = &Ps[(ty + 64) * PITCH + tx * 16];
            *(float4*)&pr0[0]  = make_float4(s0[0],  s0[1],  s0[2],  s0[3]);
            *(float4*)&pr0[4]  = make_float4(s0[4],  s0[5],  s0[6],  s0[7]);
            *(float4*)&pr0[8]  = make_float4(s0[8],  s0[9],  s0[10], s0[11]);
            *(float4*)&pr0[12] = make_float4(s0[12], s0[13], s0[14], s0[15]);
            *(float4*)&pr1[0]  = make_float4(s1[0],  s1[1],  s1[2],  s1[3]);
            *(float4*)&pr1[4]  = make_float4(s1[4],  s1[5],  s1[6],  s1[7]);
            *(float4*)&pr1[8]  = make_float4(s1[8],  s1[9],  s1[10], s1[11]);
            *(float4*)&pr1[12] = make_float4(s1[12], s1[13], s1[14], s1[15]);
        }
        __syncthreads();

        // O[row, c] += sum_k P[row,k] * V[k,c] for rows ty, ty+64
        const float* pr0 = &Ps[ty * PITCH];
        const float* pr1 = &Ps[(ty + 64) * PITCH];
        for (int k = 0; k < 64; k++) {
            float p0 = pr0[k];
            float p1 = pr1[k];
            const float* vr = &Vs[k * PITCH + tx * 16];
            float4 v0 = *(const float4*)&vr[0];
            float4 v1 = *(const float4*)&vr[4];
            float4 v2 = *(const float4*)&vr[8];
            float4 v3 = *(const float4*)&vr[12];
            o0[0]  = fmaf(p0, v0.x, o0[0]);  o0[1]  = fmaf(p0, v0.y, o0[1]);
            o0[2]  = fmaf(p0, v0.z, o0[2]);  o0[3]  = fmaf(p0, v0.w, o0[3]);
            o0[4]  = fmaf(p0, v1.x, o0[4]);  o0[5]  = fmaf(p0, v1.y, o0[5]);
            o0[6]  = fmaf(p0, v1.z, o0[6]);  o0[7]  = fmaf(p0, v1.w, o0[7]);
            o0[8]  = fmaf(p0, v2.x, o0[8]);  o0[9]  = fmaf(p0, v2.y, o0[9]);
            o0[10] = fmaf(p0, v2.z, o0[10]); o0[11] = fmaf(p0, v2.w, o0[11]);
            o0[12] = fmaf(p0, v3.x, o0[12]); o0[13] = fmaf(p0, v3.y, o0[13]);
            o0[14] = fmaf(p0, v3.z, o0[14]); o0[15] = fmaf(p0, v3.w, o0[15]);
            o1[0]  = fmaf(p1, v0.x, o1[0]);  o1[1]  = fmaf(p1, v0.y, o1[1]);
            o1[2]  = fmaf(p1, v0.z, o1[2]);  o1[3]  = fmaf(p1, v0.w, o1[3]);
            o1[4]  = fmaf(p1, v1.x, o1[4]);  o1[5]  = fmaf(p1, v1.y, o1[5]);
            o1[6]  = fmaf(p1, v1.z, o1[6]);  o1[7]  = fmaf(p1, v1.w, o1[7]);
            o1[8]  = fmaf(p1, v2.x, o1[8]);  o1[9]  = fmaf(p1, v2.y, o1[9]);
            o1[10] = fmaf(p1, v2.z, o1[10]); o1[11] = fmaf(p1, v2.w, o1[11]);
            o1[12] = fmaf(p1, v3.x, o1[12]); o1[13] = fmaf(p1, v3.y, o1[13]);
            o1[14] = fmaf(p1, v3.z, o1[14]); o1[15] = fmaf(p1, v3.w, o1[15]);
        }
    }

    // normalize + write to [B,S,D] layout (head-interleaved columns)
    float inv0 = 1.f / l0;
    float inv1 = 1.f / l1;
    float* op0 = &O[(size_t)(b * S_ + q0 + ty) * D_ + hoff + tx * 16];
    float* op1 = &O[(size_t)(b * S_ + q0 + ty + 64) * D_ + hoff + tx * 16];
    *(float4*)&op0[0]  = make_float4(o0[0]*inv0,  o0[1]*inv0,  o0[2]*inv0,  o0[3]*inv0);
    *(float4*)&op0[4]  = make_float4(o0[4]*inv0,  o0[5]*inv0,  o0[6]*inv0,  o0[7]*inv0);
    *(float4*)&op0[8]  = make_float4(o0[8]*inv0,  o0[9]*inv0,  o0[10]*inv0, o0[11]*inv0);
    *(float4*)&op0[12] = make_float4(o0[12]*inv0, o0[13]*inv0, o0[14]*inv0, o0[15]*inv0);
    *(float4*)&op1[0]  = make_float4(o1[0]*inv1,  o1[1]*inv1,  o1[2]*inv1,  o1[3]*inv1);
    *(float4*)&op1[4]  = make_float4(o1[4]*inv1,  o1[5]*inv1,  o1[6]*inv1,  o1[7]*inv1);
    *(float4*)&op1[8]  = make_float4(o1[8]*inv1,  o1[9]*inv1,  o1[10]*inv1, o1[11]*inv1);
    *(float4*)&op1[12] = make_float4(o1[12]*inv1, o1[13]*inv1, o1[14]*inv1, o1[15]*inv1);
}

// ----------------------------------------------------------------------------
// Launch: 3 projection GEMMs -> flash attention -> output GEMM
// Input order (metadata): query, value, key, Wq, bq, Wk, bk, Wv, bv, Wo, bo
// ----------------------------------------------------------------------------
extern "C" void kernel_launch(void* const* d_in, const int* in_sizes, int n_in,
                              void* d_out, int out_size)
{
    const float* query = (const float*)d_in[0];
    const float* value = (const float*)d_in[1];
    const float* key   = (const float*)d_in[2];
    const float* Wq = (const float*)d_in[3];
    const float* bq = (const float*)d_in[4];
    const float* Wk = (const float*)d_in[5];
    const float* bk = (const float*)d_in[6];
    const float* Wv = (const float*)d_in[7];
    const float* bv = (const float*)d_in[8];
    const float* Wo = (const float*)d_in[9];
    const float* bo = (const float*)d_in[10];
    float* out = (float*)d_out;

    float *Qp, *Kp, *Vp, *AOp;
    cudaGetSymbolAddress((void**)&Qp,  g_Q);
    cudaGetSymbolAddress((void**)&Kp,  g_K);
    cudaGetSymbolAddress((void**)&Vp,  g_V);
    cudaGetSymbolAddress((void**)&AOp, g_AO);

    dim3 gemm_grid(D_ / 128, M_ / 128);
    sgemm_bias_kernel<<<gemm_grid, 256>>>(query, Wq, bq, Qp, M_, D_, D_);
    sgemm_bias_kernel<<<gemm_grid, 256>>>(key,   Wk, bk, Kp, M_, D_, D_);
    sgemm_bias_kernel<<<gemm_grid, 256>>>(value, Wv, bv, Vp, M_, D_, D_);

    // smem: Q(128) + Kt(64) + Vs(64) + Ps(128) rows of PITCH floats
    const int fa_smem = (128 + 64 + 64 + 128) * PITCH * (int)sizeof(float); // 104448
    cudaFuncSetAttribute(flash_attn_kernel,
                         cudaFuncAttributeMaxDynamicSharedMemorySize, fa_smem);
    flash_attn_kernel<<<dim3(S_ / QT, H_, B_), 256, fa_smem>>>(Qp, Kp, Vp, AOp);

    sgemm_bias_kernel<<<gemm_grid, 256>>>(AOp, Wo, bo, out, M_, D_, D_);
}

// round 4
// speedup vs baseline: 2.0839x; 1.2095x over previous
#include <cuda_runtime.h>
#include <math.h>
#include <float.h>
#include <stdint.h>

// Problem constants
#define B_  4
#define S_  2048
#define H_  16
#define DK_ 64
#define D_  1024
#define M_  (B_*S_)   // 8192 rows

// Scratch (device globals: no allocation allowed in kernel_launch)
__device__ float g_Q [(size_t)M_ * D_];
__device__ float g_K [(size_t)M_ * D_];
__device__ float g_V [(size_t)M_ * D_];
__device__ float g_AO[(size_t)M_ * D_];

// ----------------------------------------------------------------------------
// helpers
// ----------------------------------------------------------------------------
__device__ __forceinline__ uint32_t s2u(const void* p) {
    return (uint32_t)__cvta_generic_to_shared(p);
}
__device__ __forceinline__ void cp_async16(uint32_t dst, const void* src) {
    asm volatile("cp.async.cg.shared.global [%0], [%1], 16;" :: "r"(dst), "l"(src));
}
__device__ __forceinline__ uint32_t f2tf(float x) {
    uint32_t r;
    asm("cvt.rna.tf32.f32 %0, %1;" : "=r"(r) : "f"(x));
    return r;
}
__device__ __forceinline__ void mma_tf32(float c[4],
                                         uint32_t a0, uint32_t a1, uint32_t a2, uint32_t a3,
                                         uint32_t b0, uint32_t b1) {
    asm volatile(
        "mma.sync.aligned.m16n8k8.row.col.f32.tf32.tf32.f32 "
        "{%0,%1,%2,%3}, {%4,%5,%6,%7}, {%8,%9}, {%0,%1,%2,%3};"
        : "+f"(c[0]), "+f"(c[1]), "+f"(c[2]), "+f"(c[3])
        : "r"(a0), "r"(a1), "r"(a2), "r"(a3), "r"(b0), "r"(b1));
}

// ----------------------------------------------------------------------------
// TF32 tensor-core GEMM + bias: C[M,N] = A[M,K] @ W[K,N] + bias[N]
// 128x128 CTA tile, 8 warps (4x2), warp tile 32x64, mma m16n8k8.
// K chunks of 32, cp.async double-buffered.
// Smem: A [128][36] (frag reads conflict-free), B [32][132].
// ----------------------------------------------------------------------------
#define APITCH 36
#define BPITCH 132
#define KC     32
#define ABUF   (128 * APITCH)   // 4608 floats
#define BBUF   (KC * BPITCH)    // 4224 floats

extern __shared__ float gm_sm[];

__global__ __launch_bounds__(256, 2)
void tf32_gemm_bias_kernel(const float* __restrict__ A, const float* __restrict__ W,
                           const float* __restrict__ bias, float* __restrict__ C,
                           int M, int N, int K)
{
    float* As[2] = { gm_sm,            gm_sm + ABUF };
    float* Bs[2] = { gm_sm + 2*ABUF,   gm_sm + 2*ABUF + BBUF };

    const int tid  = threadIdx.x;
    const int wid  = tid >> 5;
    const int lane = tid & 31;
    const int lr   = lane >> 2;   // 0..7
    const int lc   = lane & 3;    // 0..3
    const int wm   = (wid & 3) * 32;   // warp m offset in CTA tile
    const int wn   = (wid >> 2) * 64;  // warp n offset
    const int m0   = blockIdx.y * 128;
    const int n0   = blockIdx.x * 128;

    // global->smem load maps (per chunk)
    const int a_row = tid >> 1;               // wait—need 1024 float4 for A; map below per i
    (void)a_row;

    float c[2][8][4];
#pragma unroll
    for (int mt = 0; mt < 2; mt++)
#pragma unroll
        for (int nt = 0; nt < 8; nt++)
#pragma unroll
            for (int j = 0; j < 4; j++) c[mt][nt][j] = 0.f;

    const int NC = K / KC;   // 32 chunks

    // chunk loader: A tile 128x32, B tile 32x128, 4 float4 per thread each
    auto load_chunk = [&](int k0, int buf) {
#pragma unroll
        for (int i = 0; i < 4; i++) {
            int idx  = tid + i * 256;          // 0..1023
            int row  = idx >> 3;               // 0..127
            int kc   = (idx & 7) * 4;          // 0..28
            cp_async16(s2u(&As[buf][row * APITCH + kc]),
                       A + (size_t)(m0 + row) * K + k0 + kc);
        }
#pragma unroll
        for (int i = 0; i < 4; i++) {
            int idx  = tid + i * 256;
            int krow = idx >> 5;               // 0..31
            int nc   = (idx & 31) * 4;         // 0..124
            cp_async16(s2u(&Bs[buf][krow * BPITCH + nc]),
                       W + (size_t)(k0 + krow) * N + n0 + nc);
        }
    };

    load_chunk(0, 0);
    asm volatile("cp.async.commit_group;");

    for (int ch = 0; ch < NC; ch++) {
        if (ch + 1 < NC) {
            load_chunk((ch + 1) * KC, (ch + 1) & 1);
            asm volatile("cp.async.commit_group;");
            asm volatile("cp.async.wait_group 1;");
        } else {
            asm volatile("cp.async.wait_group 0;");
        }
        __syncthreads();

        const float* Ab = As[ch & 1];
        const float* Bb = Bs[ch & 1];

#pragma unroll
        for (int ks = 0; ks < 4; ks++) {
            const int kb = ks * 8;
            uint32_t af[2][4];
#pragma unroll
            for (int mt = 0; mt < 2; mt++) {
                const float* ap = &Ab[(wm + mt * 16 + lr) * APITCH + kb + lc];
                af[mt][0] = f2tf(ap[0]);
                af[mt][1] = f2tf(ap[8 * APITCH]);
                af[mt][2] = f2tf(ap[4]);
                af[mt][3] = f2tf(ap[8 * APITCH + 4]);
            }
            uint32_t bf[8][2];
#pragma unroll
            for (int nt = 0; nt < 8; nt++) {
                const float* bp = &Bb[(kb + lc) * BPITCH + wn + nt * 8 + lr];
                bf[nt][0] = f2tf(bp[0]);
                bf[nt][1] = f2tf(bp[4 * BPITCH]);
            }
#pragma unroll
            for (int mt = 0; mt < 2; mt++)
#pragma unroll
                for (int nt = 0; nt < 8; nt++)
                    mma_tf32(c[mt][nt], af[mt][0], af[mt][1], af[mt][2], af[mt][3],
                             bf[nt][0], bf[nt][1]);
        }
        __syncthreads();
    }

    // epilogue: bias + store (float2 per 8-col tile per row-half)
#pragma unroll
    for (int nt = 0; nt < 8; nt++) {
        const int col = n0 + wn + nt * 8 + lc * 2;
        const float2 bj = *(const float2*)&bias[col];
#pragma unroll
        for (int mt = 0; mt < 2; mt++) {
            const int row0 = m0 + wm + mt * 16 + lr;
            float2 v0, v1;
            v0.x = c[mt][nt][0] + bj.x;  v0.y = c[mt][nt][1] + bj.y;
            v1.x = c[mt][nt][2] + bj.x;  v1.y = c[mt][nt][3] + bj.y;
            *(float2*)&C[(size_t)row0 * N + col]       = v0;
            *(float2*)&C[(size_t)(row0 + 8) * N + col] = v1;
        }
    }
}

// ----------------------------------------------------------------------------
// Flash attention (fp32, online softmax), 2 q-rows per thread.
// (unchanged from round 3 — passing, L1-bound)
// ----------------------------------------------------------------------------
#define QT    128
#define KT    64
#define PITCH 68

extern __shared__ float fa_sm[];

__global__ __launch_bounds__(256, 2)
void flash_attn_kernel(const float* __restrict__ Q, const float* __restrict__ K,
                       const float* __restrict__ V, float* __restrict__ O)
{
    float* Qs = fa_sm;
    float* Kt = Qs + 128 * PITCH;
    float* Vs = Kt + 64 * PITCH;
    float* Ps = Vs + 64 * PITCH;

    const int tid  = threadIdx.x;
    const int q0   = blockIdx.x * QT;
    const int h    = blockIdx.y;
    const int b    = blockIdx.z;
    const int hoff = h * DK_;
    const int ty   = tid >> 2;
    const int tx   = tid & 3;

#pragma unroll
    for (int i = 0; i < 8; i++) {
        int idx = tid + i * 256;
        int row = idx >> 4;
        int cg  = (idx & 15) * 4;
        float4 v = *(const float4*)&Q[(size_t)(b * S_ + q0 + row) * D_ + hoff + cg];
        *(float4*)&Qs[row * PITCH + cg] = v;
    }

    float m0r = -FLT_MAX, m1r = -FLT_MAX;
    float l0  = 0.f,      l1  = 0.f;
    float o0[16], o1[16];
#pragma unroll
    for (int j = 0; j < 16; j++) { o0[j] = 0.f; o1[j] = 0.f; }

    for (int kt = 0; kt < S_; kt += KT) {
        __syncthreads();

#pragma unroll
        for (int i = 0; i < 4; i++) {
            int idx = tid + i * 256;
            int row = idx >> 4;
            int cg  = (idx & 15) * 4;
            const size_t gr = (size_t)(b * S_ + kt + row) * D_ + hoff + cg;
            float4 kv = *(const float4*)&K[gr];
            Kt[(cg + 0) * PITCH + row] = kv.x;
            Kt[(cg + 1) * PITCH + row] = kv.y;
            Kt[(cg + 2) * PITCH + row] = kv.z;
            Kt[(cg + 3) * PITCH + row] = kv.w;
            float4 vv = *(const float4*)&V[gr];
            *(float4*)&Vs[row * PITCH + cg] = vv;
        }
        __syncthreads();

        float s0[16], s1[16];
#pragma unroll
        for (int j = 0; j < 16; j++) { s0[j] = 0.f; s1[j] = 0.f; }
        const float* q0r = &Qs[ty * PITCH];
        const float* q1r = &Qs[(ty + 64) * PITCH];
        for (int kk = 0; kk < 64; kk++) {
            float qa = q0r[kk];
            float qb = q1r[kk];
            const float* kr = &Kt[kk * PITCH + tx * 16];
            float4 k0 = *(const float4*)&kr[0];
            float4 k1 = *(const float4*)&kr[4];
            float4 k2 = *(const float4*)&kr[8];
            float4 k3 = *(const float4*)&kr[12];
            s0[0]  = fmaf(qa, k0.x, s0[0]);  s0[1]  = fmaf(qa, k0.y, s0[1]);
            s0[2]  = fmaf(qa, k0.z, s0[2]);  s0[3]  = fmaf(qa, k0.w, s0[3]);
            s0[4]  = fmaf(qa, k1.x, s0[4]);  s0[5]  = fmaf(qa, k1.y, s0[5]);
            s0[6]  = fmaf(qa, k1.z, s0[6]);  s0[7]  = fmaf(qa, k1.w, s0[7]);
            s0[8]  = fmaf(qa, k2.x, s0[8]);  s0[9]  = fmaf(qa, k2.y, s0[9]);
            s0[10] = fmaf(qa, k2.z, s0[10]); s0[11] = fmaf(qa, k2.w, s0[11]);
            s0[12] = fmaf(qa, k3.x, s0[12]); s0[13] = fmaf(qa, k3.y, s0[13]);
            s0[14] = fmaf(qa, k3.z, s0[14]); s0[15] = fmaf(qa, k3.w, s0[15]);
            s1[0]  = fmaf(qb, k0.x, s1[0]);  s1[1]  = fmaf(qb, k0.y, s1[1]);
            s1[2]  = fmaf(qb, k0.z, s1[2]);  s1[3]  = fmaf(qb, k0.w, s1[3]);
            s1[4]  = fmaf(qb, k1.x, s1[4]);  s1[5]  = fmaf(qb, k1.y, s1[5]);
            s1[6]  = fmaf(qb, k1.z, s1[6]);  s1[7]  = fmaf(qb, k1.w, s1[7]);
            s1[8]  = fmaf(qb, k2.x, s1[8]);  s1[9]  = fmaf(qb, k2.y, s1[9]);
            s1[10] = fmaf(qb, k2.z, s1[10]); s1[11] = fmaf(qb, k2.w, s1[11]);
            s1[12] = fmaf(qb, k3.x, s1[12]); s1[13] = fmaf(qb, k3.y, s1[13]);
            s1[14] = fmaf(qb, k3.z, s1[14]); s1[15] = fmaf(qb, k3.w, s1[15]);
        }

        float t0 = -FLT_MAX, t1 = -FLT_MAX;
#pragma unroll
        for (int j = 0; j < 16; j++) {
            s0[j] *= 0.125f;
            s1[j] *= 0.125f;
            t0 = fmaxf(t0, s0[j]);
            t1 = fmaxf(t1, s1[j]);
        }
        t0 = fmaxf(t0, __shfl_xor_sync(0xffffffffu, t0, 1));
        t0 = fmaxf(t0, __shfl_xor_sync(0xffffffffu, t0, 2));
        t1 = fmaxf(t1, __shfl_xor_sync(0xffffffffu, t1, 1));
        t1 = fmaxf(t1, __shfl_xor_sync(0xffffffffu, t1, 2));

        float mn0 = fmaxf(m0r, t0);
        float mn1 = fmaxf(m1r, t1);
        float al0 = __expf(m0r - mn0);
        float al1 = __expf(m1r - mn1);
        float ps0 = 0.f, ps1 = 0.f;
#pragma unroll
        for (int j = 0; j < 16; j++) {
            float p0 = __expf(s0[j] - mn0);
            float p1 = __expf(s1[j] - mn1);
            s0[j] = p0;  ps0 += p0;
            s1[j] = p1;  ps1 += p1;
        }
        ps0 += __shfl_xor_sync(0xffffffffu, ps0, 1);
        ps0 += __shfl_xor_sync(0xffffffffu, ps0, 2);
        ps1 += __shfl_xor_sync(0xffffffffu, ps1, 1);
        ps1 += __shfl_xor_sync(0xffffffffu, ps1, 2);
        l0 = l0 * al0 + ps0;  m0r = mn0;
        l1 = l1 * al1 + ps1;  m1r = mn1;
#pragma unroll
        for (int j = 0; j < 16; j++) { o0[j] *= al0; o1[j] *= al1; }

        {
            float* pr0 = &Ps[ty * PITCH + tx * 16];
            float* pr1 = &Ps[(ty + 64) * PITCH + tx * 16];
            *(float4*)&pr0[0]  = make_float4(s0[0],  s0[1],  s0[2],  s0[3]);
            *(float4*)&pr0[4]  = make_float4(s0[4],  s0[5],  s0[6],  s0[7]);
            *(float4*)&pr0[8]  = make_float4(s0[8],  s0[9],  s0[10], s0[11]);
            *(float4*)&pr0[12] = make_float4(s0[12], s0[13], s0[14], s0[15]);
            *(float4*)&pr1[0]  = make_float4(s1[0],  s1[1],  s1[2],  s1[3]);
            *(float4*)&pr1[4]  = make_float4(s1[4],  s1[5],  s1[6],  s1[7]);
            *(float4*)&pr1[8]  = make_float4(s1[8],  s1[9],  s1[10], s1[11]);
            *(float4*)&pr1[12] = make_float4(s1[12], s1[13], s1[14], s1[15]);
        }
        __syncthreads();

        const float* pr0 = &Ps[ty * PITCH];
        const float* pr1 = &Ps[(ty + 64) * PITCH];
        for (int k = 0; k < 64; k++) {
            float p0 = pr0[k];
            float p1 = pr1[k];
            const float* vr = &Vs[k * PITCH + tx * 16];
            float4 v0 = *(const float4*)&vr[0];
            float4 v1 = *(const float4*)&vr[4];
            float4 v2 = *(const float4*)&vr[8];
            float4 v3 = *(const float4*)&vr[12];
            o0[0]  = fmaf(p0, v0.x, o0[0]);  o0[1]  = fmaf(p0, v0.y, o0[1]);
            o0[2]  = fmaf(p0, v0.z, o0[2]);  o0[3]  = fmaf(p0, v0.w, o0[3]);
            o0[4]  = fmaf(p0, v1.x, o0[4]);  o0[5]  = fmaf(p0, v1.y, o0[5]);
            o0[6]  = fmaf(p0, v1.z, o0[6]);  o0[7]  = fmaf(p0, v1.w, o0[7]);
            o0[8]  = fmaf(p0, v2.x, o0[8]);  o0[9]  = fmaf(p0, v2.y, o0[9]);
            o0[10] = fmaf(p0, v2.z, o0[10]); o0[11] = fmaf(p0, v2.w, o0[11]);
            o0[12] = fmaf(p0, v3.x, o0[12]); o0[13] = fmaf(p0, v3.y, o0[13]);
            o0[14] = fmaf(p0, v3.z, o0[14]); o0[15] = fmaf(p0, v3.w, o0[15]);
            o1[0]  = fmaf(p1, v0.x, o1[0]);  o1[1]  = fmaf(p1, v0.y, o1[1]);
            o1[2]  = fmaf(p1, v0.z, o1[2]);  o1[3]  = fmaf(p1, v0.w, o1[3]);
            o1[4]  = fmaf(p1, v1.x, o1[4]);  o1[5]  = fmaf(p1, v1.y, o1[5]);
            o1[6]  = fmaf(p1, v1.z, o1[6]);  o1[7]  = fmaf(p1, v1.w, o1[7]);
            o1[8]  = fmaf(p1, v2.x, o1[8]);  o1[9]  = fmaf(p1, v2.y, o1[9]);
            o1[10] = fmaf(p1, v2.z, o1[10]); o1[11] = fmaf(p1, v2.w, o1[11]);
            o1[12] = fmaf(p1, v3.x, o1[12]); o1[13] = fmaf(p1, v3.y, o1[13]);
            o1[14] = fmaf(p1, v3.z, o1[14]); o1[15] = fmaf(p1, v3.w, o1[15]);
        }
    }

    float inv0 = 1.f / l0;
    float inv1 = 1.f / l1;
    float* op0 = &O[(size_t)(b * S_ + q0 + ty) * D_ + hoff + tx * 16];
    float* op1 = &O[(size_t)(b * S_ + q0 + ty + 64) * D_ + hoff + tx * 16];
    *(float4*)&op0[0]  = make_float4(o0[0]*inv0,  o0[1]*inv0,  o0[2]*inv0,  o0[3]*inv0);
    *(float4*)&op0[4]  = make_float4(o0[4]*inv0,  o0[5]*inv0,  o0[6]*inv0,  o0[7]*inv0);
    *(float4*)&op0[8]  = make_float4(o0[8]*inv0,  o0[9]*inv0,  o0[10]*inv0, o0[11]*inv0);
    *(float4*)&op0[12] = make_float4(o0[12]*inv0, o0[13]*inv0, o0[14]*inv0, o0[15]*inv0);
    *(float4*)&op1[0]  = make_float4(o1[0]*inv1,  o1[1]*inv1,  o1[2]*inv1,  o1[3]*inv1);
    *(float4*)&op1[4]  = make_float4(o1[4]*inv1,  o1[5]*inv1,  o1[6]*inv1,  o1[7]*inv1);
    *(float4*)&op1[8]  = make_float4(o1[8]*inv1,  o1[9]*inv1,  o1[10]*inv1, o1[11]*inv1);
    *(float4*)&op1[12] = make_float4(o1[12]*inv1, o1[13]*inv1, o1[14]*inv1, o1[15]*inv1);
}

// ----------------------------------------------------------------------------
// Launch
// ----------------------------------------------------------------------------
extern "C" void kernel_launch(void* const* d_in, const int* in_sizes, int n_in,
                              void* d_out, int out_size)
{
    const float* query = (const float*)d_in[0];
    const float* value = (const float*)d_in[1];
    const float* key   = (const float*)d_in[2];
    const float* Wq = (const float*)d_in[3];
    const float* bq = (const float*)d_in[4];
    const float* Wk = (const float*)d_in[5];
    const float* bk = (const float*)d_in[6];
    const float* Wv = (const float*)d_in[7];
    const float* bv = (const float*)d_in[8];
    const float* Wo = (const float*)d_in[9];
    const float* bo = (const float*)d_in[10];
    float* out = (float*)d_out;

    float *Qp, *Kp, *Vp, *AOp;
    cudaGetSymbolAddress((void**)&Qp,  g_Q);
    cudaGetSymbolAddress((void**)&Kp,  g_K);
    cudaGetSymbolAddress((void**)&Vp,  g_V);
    cudaGetSymbolAddress((void**)&AOp, g_AO);

    const int gemm_smem = 2 * (ABUF + BBUF) * (int)sizeof(float);  // 70656 B
    cudaFuncSetAttribute(tf32_gemm_bias_kernel,
                         cudaFuncAttributeMaxDynamicSharedMemorySize, gemm_smem);

    dim3 gemm_grid(D_ / 128, M_ / 128);
    tf32_gemm_bias_kernel<<<gemm_grid, 256, gemm_smem>>>(query, Wq, bq, Qp, M_, D_, D_);
    tf32_gemm_bias_kernel<<<gemm_grid, 256, gemm_smem>>>(key,   Wk, bk, Kp, M_, D_, D_);
    tf32_gemm_bias_kernel<<<gemm_grid, 256, gemm_smem>>>(value, Wv, bv, Vp, M_, D_, D_);

    const int fa_smem = (128 + 64 + 64 + 128) * PITCH * (int)sizeof(float); // 104448
    cudaFuncSetAttribute(flash_attn_kernel,
                         cudaFuncAttributeMaxDynamicSharedMemorySize, fa_smem);
    flash_attn_kernel<<<dim3(S_ / QT, H_, B_), 256, fa_smem>>>(Qp, Kp, Vp, AOp);

    tf32_gemm_bias_kernel<<<gemm_grid, 256, gemm_smem>>>(AOp, Wo, bo, out, M_, D_, D_);
}

// round 6
// speedup vs baseline: 3.8238x; 1.8349x over previous
#include <cuda_runtime.h>
#include <math.h>
#include <float.h>
#include <stdint.h>

// Problem constants
#define B_  4
#define S_  2048
#define H_  16
#define DK_ 64
#define D_  1024
#define M_  (B_*S_)   // 8192 rows

// Scratch (device globals: no allocation allowed in kernel_launch)
__device__ float g_Q [(size_t)M_ * D_];
__device__ float g_K [(size_t)M_ * D_];
__device__ float g_V [(size_t)M_ * D_];
__device__ float g_AO[(size_t)M_ * D_];

// ----------------------------------------------------------------------------
// helpers
// ----------------------------------------------------------------------------
__device__ __forceinline__ uint32_t s2u(const void* p) {
    return (uint32_t)__cvta_generic_to_shared(p);
}
__device__ __forceinline__ void cp_async16(uint32_t dst, const void* src) {
    asm volatile("cp.async.cg.shared.global [%0], [%1], 16;" :: "r"(dst), "l"(src));
}
__device__ __forceinline__ uint32_t f2tf(float x) {
    uint32_t r;
    asm("cvt.rna.tf32.f32 %0, %1;" : "=r"(r) : "f"(x));
    return r;
}
__device__ __forceinline__ void mma_tf32(float c[4],
                                         uint32_t a0, uint32_t a1, uint32_t a2, uint32_t a3,
                                         uint32_t b0, uint32_t b1) {
    asm volatile(
        "mma.sync.aligned.m16n8k8.row.col.f32.tf32.tf32.f32 "
        "{%0,%1,%2,%3}, {%4,%5,%6,%7}, {%8,%9}, {%0,%1,%2,%3};"
        : "+f"(c[0]), "+f"(c[1]), "+f"(c[2]), "+f"(c[3])
        : "r"(a0), "r"(a1), "r"(a2), "r"(a3), "r"(b0), "r"(b1));
}

// Fast exp on FMA/ALU pipes only (no MUFU, no F2I/I2F SASS converts).
// exp(x) = 2^(x*log2e); n = rne(y) via magic-number, f in [-0.5,0.5],
// 2^f by degree-5 poly (max rel err ~1e-7), scale via exponent bits.
// Input clamped to [-87, 0]: below -87 the true value (<1.6e-38) is
// indistinguishable from 0 for softmax accumulation, and the clamp keeps
// the magic-number rounding in its valid |y| < 2^21 domain (the -1e30
// sentinel previously wrapped the exponent and produced 2^127 -> NaN).
__device__ __forceinline__ float fexp(float x) {
    x = fmaxf(x, -87.0f);
    const float MAGIC = 12582912.0f;           // 1.5 * 2^23
    float y  = x * 1.44269504089f;
    float t  = y + MAGIC;
    int   e  = __float_as_int(t) - 0x4B400000; // integer n, valid after clamp
    float nf = t - MAGIC;
    float f  = y - nf;
    float p  = 1.33335581e-3f;
    p = fmaf(p, f, 9.61812910e-3f);
    p = fmaf(p, f, 5.55041087e-2f);
    p = fmaf(p, f, 2.40226507e-1f);
    p = fmaf(p, f, 6.93147180e-1f);
    p = fmaf(p, f, 1.0f);
    float sc = __int_as_float((e + 127) << 23);  // e in [-126, 0] after clamp
    return p * sc;
}

// ----------------------------------------------------------------------------
// TF32 tensor-core GEMM + bias (unchanged from round 4 — passing)
// ----------------------------------------------------------------------------
#define APITCH 36
#define BPITCH 132
#define KC     32
#define ABUF   (128 * APITCH)
#define BBUF   (KC * BPITCH)

extern __shared__ float gm_sm[];

__global__ __launch_bounds__(256, 2)
void tf32_gemm_bias_kernel(const float* __restrict__ A, const float* __restrict__ W,
                           const float* __restrict__ bias, float* __restrict__ C,
                           int M, int N, int K)
{
    float* As[2] = { gm_sm,            gm_sm + ABUF };
    float* Bs[2] = { gm_sm + 2*ABUF,   gm_sm + 2*ABUF + BBUF };

    const int tid  = threadIdx.x;
    const int wid  = tid >> 5;
    const int lane = tid & 31;
    const int lr   = lane >> 2;
    const int lc   = lane & 3;
    const int wm   = (wid & 3) * 32;
    const int wn   = (wid >> 2) * 64;
    const int m0   = blockIdx.y * 128;
    const int n0   = blockIdx.x * 128;

    float c[2][8][4];
#pragma unroll
    for (int mt = 0; mt < 2; mt++)
#pragma unroll
        for (int nt = 0; nt < 8; nt++)
#pragma unroll
            for (int j = 0; j < 4; j++) c[mt][nt][j] = 0.f;

    const int NC = K / KC;

    auto load_chunk = [&](int k0, int buf) {
#pragma unroll
        for (int i = 0; i < 4; i++) {
            int idx  = tid + i * 256;
            int row  = idx >> 3;
            int kc   = (idx & 7) * 4;
            cp_async16(s2u(&As[buf][row * APITCH + kc]),
                       A + (size_t)(m0 + row) * K + k0 + kc);
        }
#pragma unroll
        for (int i = 0; i < 4; i++) {
            int idx  = tid + i * 256;
            int krow = idx >> 5;
            int nc   = (idx & 31) * 4;
            cp_async16(s2u(&Bs[buf][krow * BPITCH + nc]),
                       W + (size_t)(k0 + krow) * N + n0 + nc);
        }
    };

    load_chunk(0, 0);
    asm volatile("cp.async.commit_group;");

    for (int ch = 0; ch < NC; ch++) {
        if (ch + 1 < NC) {
            load_chunk((ch + 1) * KC, (ch + 1) & 1);
            asm volatile("cp.async.commit_group;");
            asm volatile("cp.async.wait_group 1;");
        } else {
            asm volatile("cp.async.wait_group 0;");
        }
        __syncthreads();

        const float* Ab = As[ch & 1];
        const float* Bb = Bs[ch & 1];

#pragma unroll
        for (int ks = 0; ks < 4; ks++) {
            const int kb = ks * 8;
            uint32_t af[2][4];
#pragma unroll
            for (int mt = 0; mt < 2; mt++) {
                const float* ap = &Ab[(wm + mt * 16 + lr) * APITCH + kb + lc];
                af[mt][0] = f2tf(ap[0]);
                af[mt][1] = f2tf(ap[8 * APITCH]);
                af[mt][2] = f2tf(ap[4]);
                af[mt][3] = f2tf(ap[8 * APITCH + 4]);
            }
            uint32_t bf[8][2];
#pragma unroll
            for (int nt = 0; nt < 8; nt++) {
                const float* bp = &Bb[(kb + lc) * BPITCH + wn + nt * 8 + lr];
                bf[nt][0] = f2tf(bp[0]);
                bf[nt][1] = f2tf(bp[4 * BPITCH]);
            }
#pragma unroll
            for (int mt = 0; mt < 2; mt++)
#pragma unroll
                for (int nt = 0; nt < 8; nt++)
                    mma_tf32(c[mt][nt], af[mt][0], af[mt][1], af[mt][2], af[mt][3],
                             bf[nt][0], bf[nt][1]);
        }
        __syncthreads();
    }

#pragma unroll
    for (int nt = 0; nt < 8; nt++) {
        const int col = n0 + wn + nt * 8 + lc * 2;
        const float2 bj = *(const float2*)&bias[col];
#pragma unroll
        for (int mt = 0; mt < 2; mt++) {
            const int row0 = m0 + wm + mt * 16 + lr;
            float2 v0, v1;
            v0.x = c[mt][nt][0] + bj.x;  v0.y = c[mt][nt][1] + bj.y;
            v1.x = c[mt][nt][2] + bj.x;  v1.y = c[mt][nt][3] + bj.y;
            *(float2*)&C[(size_t)row0 * N + col]       = v0;
            *(float2*)&C[(size_t)(row0 + 8) * N + col] = v1;
        }
    }
}

// ----------------------------------------------------------------------------
// Flash attention v3 (fp32, online softmax), 4 q-rows x 8 cols per thread.
// CTA = (b, h, 128 q-rows), KV tiles of 64, 256 threads.
// ty = tid>>3 (rows ty, +32, +64, +96), tx = tid&7 (cols tx*8..tx*8+7).
// Kt transpose-store: conflict-free scalar map. Key/dk rows XOR-swizzled so
// fragment LDS.128 are conflict-free. exp on FMA pipe (no MUFU).
// ----------------------------------------------------------------------------
#define QT    128
#define KT    64
#define PITCH 68

// XOR swizzle within a 64-float row: keeps 4-float groups intact.
__device__ __forceinline__ int swz(int c) { return c ^ ((c & 32) >> 3); }

extern __shared__ float fa_sm[];

__global__ __launch_bounds__(256, 2)
void flash_attn_kernel(const float* __restrict__ Q, const float* __restrict__ K,
                       const float* __restrict__ V, float* __restrict__ O)
{
    float* Qs = fa_sm;                    // [128][PITCH] Q natural
    float* Kt = Qs + 128 * PITCH;         // [64][PITCH]  Kt[dk][key_swz]
    float* Vs = Kt + 64 * PITCH;          // [64][PITCH]  Vs[key][dk_swz]
    float* Ps = Vs + 64 * PITCH;          // [128][PITCH] probs

    const int tid  = threadIdx.x;
    const int q0   = blockIdx.x * QT;
    const int h    = blockIdx.y;
    const int b    = blockIdx.z;
    const int hoff = h * DK_;
    const int ty   = tid >> 3;   // 0..31
    const int tx   = tid & 7;    // 0..7
    const int c0   = swz(tx * 8);
    const int c1   = swz(tx * 8 + 4);

    // Load Q tile (128x64), natural layout
#pragma unroll
    for (int i = 0; i < 8; i++) {
        int idx = tid + i * 256;
        int row = idx >> 4;
        int cg  = (idx & 15) * 4;
        float4 v = *(const float4*)&Q[(size_t)(b * S_ + q0 + row) * D_ + hoff + cg];
        *(float4*)&Qs[row * PITCH + cg] = v;
    }

    float mr[4], lr_[4];
    float o[4][8];
#pragma unroll
    for (int r = 0; r < 4; r++) {
        mr[r] = -1e30f;  lr_[r] = 0.f;
#pragma unroll
        for (int j = 0; j < 8; j++) o[r][j] = 0.f;
    }

    for (int kt = 0; kt < S_; kt += KT) {
        __syncthreads();  // prior-iter Ps/Vs reads done (and Qs stores on iter 0)

        // K: conflict-free transpose store. lane map: key = u&63, cg = ((u>>6)&15)*4
#pragma unroll
        for (int i = 0; i < 4; i++) {
            int u   = tid + i * 256;
            int key = u & 63;
            int cg  = ((u >> 6) & 15) * 4;
            float4 kv = *(const float4*)&K[(size_t)(b * S_ + kt + key) * D_ + hoff + cg];
            int kp  = swz(key);
            Kt[(cg + 0) * PITCH + kp] = kv.x;
            Kt[(cg + 1) * PITCH + kp] = kv.y;
            Kt[(cg + 2) * PITCH + kp] = kv.z;
            Kt[(cg + 3) * PITCH + kp] = kv.w;
        }
        // V: natural store, dk swizzled
#pragma unroll
        for (int i = 0; i < 4; i++) {
            int u   = tid + i * 256;
            int row = u >> 4;            // 0..63
            int cg  = (u & 15) * 4;
            float4 vv = *(const float4*)&V[(size_t)(b * S_ + kt + row) * D_ + hoff + cg];
            *(float4*)&Vs[row * PITCH + swz(cg)] = vv;
        }
        __syncthreads();

        // S[r][j] = Q[row_r,:] . K[tx*8+j,:]
        float s[4][8];
#pragma unroll
        for (int r = 0; r < 4; r++)
#pragma unroll
            for (int j = 0; j < 8; j++) s[r][j] = 0.f;

        const float* qp0 = &Qs[ty * PITCH];
        const float* qp1 = &Qs[(ty + 32) * PITCH];
        const float* qp2 = &Qs[(ty + 64) * PITCH];
        const float* qp3 = &Qs[(ty + 96) * PITCH];
        for (int kk = 0; kk < 64; kk++) {
            float qa = qp0[kk];
            float qb = qp1[kk];
            float qc = qp2[kk];
            float qd = qp3[kk];
            const float* kr = &Kt[kk * PITCH];
            float4 k0 = *(const float4*)&kr[c0];
            float4 k1 = *(const float4*)&kr[c1];
            s[0][0] = fmaf(qa, k0.x, s[0][0]); s[0][1] = fmaf(qa, k0.y, s[0][1]);
            s[0][2] = fmaf(qa, k0.z, s[0][2]); s[0][3] = fmaf(qa, k0.w, s[0][3]);
            s[0][4] = fmaf(qa, k1.x, s[0][4]); s[0][5] = fmaf(qa, k1.y, s[0][5]);
            s[0][6] = fmaf(qa, k1.z, s[0][6]); s[0][7] = fmaf(qa, k1.w, s[0][7]);
            s[1][0] = fmaf(qb, k0.x, s[1][0]); s[1][1] = fmaf(qb, k0.y, s[1][1]);
            s[1][2] = fmaf(qb, k0.z, s[1][2]); s[1][3] = fmaf(qb, k0.w, s[1][3]);
            s[1][4] = fmaf(qb, k1.x, s[1][4]); s[1][5] = fmaf(qb, k1.y, s[1][5]);
            s[1][6] = fmaf(qb, k1.z, s[1][6]); s[1][7] = fmaf(qb, k1.w, s[1][7]);
            s[2][0] = fmaf(qc, k0.x, s[2][0]); s[2][1] = fmaf(qc, k0.y, s[2][1]);
            s[2][2] = fmaf(qc, k0.z, s[2][2]); s[2][3] = fmaf(qc, k0.w, s[2][3]);
            s[2][4] = fmaf(qc, k1.x, s[2][4]); s[2][5] = fmaf(qc, k1.y, s[2][5]);
            s[2][6] = fmaf(qc, k1.z, s[2][6]); s[2][7] = fmaf(qc, k1.w, s[2][7]);
            s[3][0] = fmaf(qd, k0.x, s[3][0]); s[3][1] = fmaf(qd, k0.y, s[3][1]);
            s[3][2] = fmaf(qd, k0.z, s[3][2]); s[3][3] = fmaf(qd, k0.w, s[3][3]);
            s[3][4] = fmaf(qd, k1.x, s[3][4]); s[3][5] = fmaf(qd, k1.y, s[3][5]);
            s[3][6] = fmaf(qd, k1.z, s[3][6]); s[3][7] = fmaf(qd, k1.w, s[3][7]);
        }

        // per-row softmax update (reduce across 8-thread tx octet)
#pragma unroll
        for (int r = 0; r < 4; r++) {
            float tmax = -1e30f;
#pragma unroll
            for (int j = 0; j < 8; j++) {
                s[r][j] *= 0.125f;   // 1/sqrt(64)
                tmax = fmaxf(tmax, s[r][j]);
            }
            tmax = fmaxf(tmax, __shfl_xor_sync(0xffffffffu, tmax, 1));
            tmax = fmaxf(tmax, __shfl_xor_sync(0xffffffffu, tmax, 2));
            tmax = fmaxf(tmax, __shfl_xor_sync(0xffffffffu, tmax, 4));

            float mn    = fmaxf(mr[r], tmax);
            float alpha = fexp(mr[r] - mn);
            float psum  = 0.f;
#pragma unroll
            for (int j = 0; j < 8; j++) {
                float p = fexp(s[r][j] - mn);
                s[r][j] = p;
                psum += p;
            }
            psum += __shfl_xor_sync(0xffffffffu, psum, 1);
            psum += __shfl_xor_sync(0xffffffffu, psum, 2);
            psum += __shfl_xor_sync(0xffffffffu, psum, 4);
            lr_[r] = lr_[r] * alpha + psum;
            mr[r]  = mn;
#pragma unroll
            for (int j = 0; j < 8; j++) o[r][j] *= alpha;
        }

        // publish probs
#pragma unroll
        for (int r = 0; r < 4; r++) {
            float* pr = &Ps[(ty + 32 * r) * PITCH + tx * 8];
            *(float4*)&pr[0] = make_float4(s[r][0], s[r][1], s[r][2], s[r][3]);
            *(float4*)&pr[4] = make_float4(s[r][4], s[r][5], s[r][6], s[r][7]);
        }
        __syncthreads();

        // O[row_r, c] += sum_k P[row_r,k] * V[k,c]
        const float* pp0 = &Ps[ty * PITCH];
        const float* pp1 = &Ps[(ty + 32) * PITCH];
        const float* pp2 = &Ps[(ty + 64) * PITCH];
        const float* pp3 = &Ps[(ty + 96) * PITCH];
        for (int k = 0; k < 64; k++) {
            float p0 = pp0[k];
            float p1 = pp1[k];
            float p2 = pp2[k];
            float p3 = pp3[k];
            const float* vr = &Vs[k * PITCH];
            float4 v0 = *(const float4*)&vr[c0];
            float4 v1 = *(const float4*)&vr[c1];
            o[0][0] = fmaf(p0, v0.x, o[0][0]); o[0][1] = fmaf(p0, v0.y, o[0][1]);
            o[0][2] = fmaf(p0, v0.z, o[0][2]); o[0][3] = fmaf(p0, v0.w, o[0][3]);
            o[0][4] = fmaf(p0, v1.x, o[0][4]); o[0][5] = fmaf(p0, v1.y, o[0][5]);
            o[0][6] = fmaf(p0, v1.z, o[0][6]); o[0][7] = fmaf(p0, v1.w, o[0][7]);
            o[1][0] = fmaf(p1, v0.x, o[1][0]); o[1][1] = fmaf(p1, v0.y, o[1][1]);
            o[1][2] = fmaf(p1, v0.z, o[1][2]); o[1][3] = fmaf(p1, v0.w, o[1][3]);
            o[1][4] = fmaf(p1, v1.x, o[1][4]); o[1][5] = fmaf(p1, v1.y, o[1][5]);
            o[1][6] = fmaf(p1, v1.z, o[1][6]); o[1][7] = fmaf(p1, v1.w, o[1][7]);
            o[2][0] = fmaf(p2, v0.x, o[2][0]); o[2][1] = fmaf(p2, v0.y, o[2][1]);
            o[2][2] = fmaf(p2, v0.z, o[2][2]); o[2][3] = fmaf(p2, v0.w, o[2][3]);
            o[2][4] = fmaf(p2, v1.x, o[2][4]); o[2][5] = fmaf(p2, v1.y, o[2][5]);
            o[2][6] = fmaf(p2, v1.z, o[2][6]); o[2][7] = fmaf(p2, v1.w, o[2][7]);
            o[3][0] = fmaf(p3, v0.x, o[3][0]); o[3][1] = fmaf(p3, v0.y, o[3][1]);
            o[3][2] = fmaf(p3, v0.z, o[3][2]); o[3][3] = fmaf(p3, v0.w, o[3][3]);
            o[3][4] = fmaf(p3, v1.x, o[3][4]); o[3][5] = fmaf(p3, v1.y, o[3][5]);
            o[3][6] = fmaf(p3, v1.z, o[3][6]); o[3][7] = fmaf(p3, v1.w, o[3][7]);
        }
    }

    // normalize + write to [B,S,D] layout
#pragma unroll
    for (int r = 0; r < 4; r++) {
        float inv = 1.f / lr_[r];
        float* op = &O[(size_t)(b * S_ + q0 + ty + 32 * r) * D_ + hoff + tx * 8];
        *(float4*)&op[0] = make_float4(o[r][0]*inv, o[r][1]*inv, o[r][2]*inv, o[r][3]*inv);
        *(float4*)&op[4] = make_float4(o[r][4]*inv, o[r][5]*inv, o[r][6]*inv, o[r][7]*inv);
    }
}

// ----------------------------------------------------------------------------
// Launch
// ----------------------------------------------------------------------------
extern "C" void kernel_launch(void* const* d_in, const int* in_sizes, int n_in,
                              void* d_out, int out_size)
{
    const float* query = (const float*)d_in[0];
    const float* value = (const float*)d_in[1];
    const float* key   = (const float*)d_in[2];
    const float* Wq = (const float*)d_in[3];
    const float* bq = (const float*)d_in[4];
    const float* Wk = (const float*)d_in[5];
    const float* bk = (const float*)d_in[6];
    const float* Wv = (const float*)d_in[7];
    const float* bv = (const float*)d_in[8];
    const float* Wo = (const float*)d_in[9];
    const float* bo = (const float*)d_in[10];
    float* out = (float*)d_out;

    float *Qp, *Kp, *Vp, *AOp;
    cudaGetSymbolAddress((void**)&Qp,  g_Q);
    cudaGetSymbolAddress((void**)&Kp,  g_K);
    cudaGetSymbolAddress((void**)&Vp,  g_V);
    cudaGetSymbolAddress((void**)&AOp, g_AO);

    const int gemm_smem = 2 * (ABUF + BBUF) * (int)sizeof(float);  // 70656 B
    cudaFuncSetAttribute(tf32_gemm_bias_kernel,
                         cudaFuncAttributeMaxDynamicSharedMemorySize, gemm_smem);

    dim3 gemm_grid(D_ / 128, M_ / 128);
    tf32_gemm_bias_kernel<<<gemm_grid, 256, gemm_smem>>>(query, Wq, bq, Qp, M_, D_, D_);
    tf32_gemm_bias_kernel<<<gemm_grid, 256, gemm_smem>>>(key,   Wk, bk, Kp, M_, D_, D_);
    tf32_gemm_bias_kernel<<<gemm_grid, 256, gemm_smem>>>(value, Wv, bv, Vp, M_, D_, D_);

    const int fa_smem = (128 + 64 + 64 + 128) * PITCH * (int)sizeof(float); // 104448
    cudaFuncSetAttribute(flash_attn_kernel,
                         cudaFuncAttributeMaxDynamicSharedMemorySize, fa_smem);
    flash_attn_kernel<<<dim3(S_ / QT, H_, B_), 256, fa_smem>>>(Qp, Kp, Vp, AOp);

    tf32_gemm_bias_kernel<<<gemm_grid, 256, gemm_smem>>>(AOp, Wo, bo, out, M_, D_, D_);
}